// round 2
// baseline (speedup 1.0000x reference)
#include <cuda_runtime.h>
#include <cstdint>

// Problem dims
#define N_B   64
#define I_DIM 256
#define H_DIM 1024
#define O_DIM 18
#define T_DIM 500
#define PAIRS (N_B * T_DIM)          // 32000 (n,t) pairs

// Recurrence constants (match jnp.float32(math.exp(...)) etc.)
#define D1 0.9048374180359595f       // exp(-1/10)
#define C1 0.2718281828459045f       // e/10
#define D2 0.36787944117144233f      // exp(-1)
#define C2 2.718281828459045f        // e
#define THETA 10.0f
#define REFSCALE -20.0f              // -scaleRef*theta

// ---- scratch (static device arrays; no allocation allowed) ----
__device__ float g_W1t[(size_t)I_DIM * H_DIM];                 // W1 transposed [i][h]
__device__ float g_y1[(size_t)PAIRS * H_DIM];                  // layer-1 pre-psp
__device__ float g_s1[(size_t)PAIRS * H_DIM];                  // layer-1 spikes
__device__ float g_y2[(size_t)PAIRS * O_DIM];                  // layer-2 pre-psp
__device__ unsigned char g_lists[(size_t)PAIRS * 256];         // active input idx per (n,t)
__device__ int g_counts[PAIRS];

// ---------------------------------------------------------------------------
// Kernel 1: build per-(n,t) active-input lists from binary spike input.
// spike layout: [n][i][t]. Block = (n, 32-t chunk), 256 threads.
// ---------------------------------------------------------------------------
__global__ void build_lists(const float* __restrict__ spike) {
    __shared__ float flags[I_DIM][32];
    int n  = blockIdx.x;             // 0..63
    int t0 = blockIdx.y * 32;        // t chunk
    int tid = threadIdx.x;
    int tl  = tid & 31;              // t lane
    int io  = tid >> 5;              // 0..7 i offset

    #pragma unroll 4
    for (int ic = 0; ic < 32; ic++) {
        int i = ic * 8 + io;
        int t = t0 + tl;
        float v = 0.f;
        if (t < T_DIM) v = spike[((size_t)(n * I_DIM + i)) * T_DIM + t];
        flags[i][tl] = v;
    }
    __syncthreads();

    if (tid < 32) {
        int t = t0 + tid;
        if (t < T_DIM) {
            int m = n * T_DIM + t;
            unsigned char* lp = g_lists + (size_t)m * 256;
            int cnt = 0;
            for (int i = 0; i < I_DIM; i++) {
                if (flags[i][tid] != 0.f) lp[cnt++] = (unsigned char)i;
            }
            g_counts[m] = cnt;
        }
    }
}

// ---------------------------------------------------------------------------
// Kernel 2: transpose W1 [H][I] -> W1t [I][H]
// ---------------------------------------------------------------------------
__global__ void transpose_w1(const float* __restrict__ W1) {
    __shared__ float tile[32][33];
    int i0 = blockIdx.x * 32;
    int h0 = blockIdx.y * 32;
    int tx = threadIdx.x, ty = threadIdx.y;   // (32, 8)
    #pragma unroll
    for (int r = 0; r < 32; r += 8)
        tile[ty + r][tx] = W1[(size_t)(h0 + ty + r) * I_DIM + i0 + tx];
    __syncthreads();
    #pragma unroll
    for (int r = 0; r < 32; r += 8)
        g_W1t[(size_t)(i0 + ty + r) * H_DIM + h0 + tx] = tile[tx][ty + r];
}

// ---------------------------------------------------------------------------
// Kernel 3: sparse GEMM1. y1[m][h] = sum over active i of W1t[i][h].
// Exact (spike values are exactly 1.0 -> pure adds).
// Grid: (100 pair-chunks, 8 h-tiles). Block 256: 128 h-lanes x 2 pair-subsets.
// h-tile of 128 keeps a 128KB W1t slice hot in L1.
// ---------------------------------------------------------------------------
__global__ void gather_y1() {
    int h    = blockIdx.y * 128 + (threadIdx.x & 127);
    int sub  = threadIdx.x >> 7;                 // 0/1
    int base = blockIdx.x * (PAIRS / 100);       // 320 pairs per chunk

    for (int m = base + sub; m < base + 320; m += 2) {
        int cnt = g_counts[m];
        const unsigned char* lp = g_lists + (size_t)m * 256;
        float acc = 0.f;
        int j = 0;
        for (; j + 4 <= cnt; j += 4) {
            uchar4 u = *(const uchar4*)(lp + j);
            float a0 = g_W1t[(size_t)u.x * H_DIM + h];
            float a1 = g_W1t[(size_t)u.y * H_DIM + h];
            float a2 = g_W1t[(size_t)u.z * H_DIM + h];
            float a3 = g_W1t[(size_t)u.w * H_DIM + h];
            acc += a0; acc += a1; acc += a2; acc += a3;
        }
        for (; j < cnt; j++) acc += g_W1t[(size_t)lp[j] * H_DIM + h];
        g_y1[(size_t)m * H_DIM + h] = acc;
    }
}

// ---------------------------------------------------------------------------
// Kernel 4: fused psp + spike_layer scan over time, layer 1.
// One thread per (n,h) sequence. y1/s1 layout [n][t][h] -> coalesced.
// ---------------------------------------------------------------------------
__global__ void scan_layer1() {
    int n = blockIdx.x >> 2;
    int h = ((blockIdx.x & 3) << 8) + threadIdx.x;
    const float* yp = g_y1 + (size_t)n * T_DIM * H_DIM + h;
    float*       sp = g_s1 + (size_t)n * T_DIM * H_DIM + h;
    float p1 = 0.f, a1 = 0.f, p2 = 0.f, a2 = 0.f;
    for (int t = 0; t < T_DIM; t++) {
        float y = yp[(size_t)t * H_DIM];
        a1 = D1 * (a1 + p1);          // psp alpha state
        p1 = D1 * p1 + y;
        a2 = D2 * (a2 + p2);          // refractory alpha state
        float u = C1 * a1 + C2 * a2;  // membrane = psp_out + refractory
        float s = (u - THETA >= 0.f) ? 1.0f : 0.0f;
        p2 = D2 * p2 + REFSCALE * s;
        sp[(size_t)t * H_DIM] = s;
    }
}

// ---------------------------------------------------------------------------
// Kernel 5: GEMM2. y2[m][o] = sum_h s1[m][h] * W2[o][h].
// Warp per (n,t) pair; W2 (73KB) stays L1-resident; zero-skip on binary s1.
// ---------------------------------------------------------------------------
__global__ void gemm2_kernel(const float* __restrict__ W2) {
    int w    = threadIdx.x >> 5;
    int lane = threadIdx.x & 31;
    int base = blockIdx.x * 64;
    for (int it = 0; it < 8; it++) {
        int m = base + it * 8 + w;
        const float4* row = (const float4*)(g_s1 + (size_t)m * H_DIM);
        float acc[O_DIM];
        #pragma unroll
        for (int o = 0; o < O_DIM; o++) acc[o] = 0.f;

        #pragma unroll
        for (int j = 0; j < 8; j++) {
            float4 v = row[lane + 32 * j];
            if (v.x == 0.f && v.y == 0.f && v.z == 0.f && v.w == 0.f) continue;
            int hb = (lane + 32 * j) * 4;
            #pragma unroll
            for (int o = 0; o < O_DIM; o++) {
                float4 wv = *(const float4*)(W2 + (size_t)o * H_DIM + hb);
                acc[o] += v.x * wv.x + v.y * wv.y + v.z * wv.z + v.w * wv.w;
            }
        }
        #pragma unroll
        for (int o = 0; o < O_DIM; o++) {
            #pragma unroll
            for (int off = 16; off > 0; off >>= 1)
                acc[o] += __shfl_down_sync(0xffffffffu, acc[o], off);
        }
        if (lane == 0) {
            float* outp = g_y2 + (size_t)m * O_DIM;
            #pragma unroll
            for (int o = 0; o < O_DIM; o++) outp[o] = acc[o];
        }
    }
}

// ---------------------------------------------------------------------------
// Kernel 6: fused psp + spike scan, layer 2. Writes final output [n][o][t].
// ---------------------------------------------------------------------------
__global__ void scan_layer2(float* __restrict__ out) {
    int idx = blockIdx.x * blockDim.x + threadIdx.x;
    if (idx >= N_B * O_DIM) return;
    int n = idx / O_DIM;
    int o = idx - n * O_DIM;
    const float* yp = g_y2 + (size_t)n * T_DIM * O_DIM + o;
    float*       op = out + (size_t)idx * T_DIM;
    float p1 = 0.f, a1 = 0.f, p2 = 0.f, a2 = 0.f;
    for (int t = 0; t < T_DIM; t++) {
        float y = yp[(size_t)t * O_DIM];
        a1 = D1 * (a1 + p1);
        p1 = D1 * p1 + y;
        a2 = D2 * (a2 + p2);
        float u = C1 * a1 + C2 * a2;
        float s = (u - THETA >= 0.f) ? 1.0f : 0.0f;
        p2 = D2 * p2 + REFSCALE * s;
        op[t] = s;
    }
}

// ---------------------------------------------------------------------------
extern "C" void kernel_launch(void* const* d_in, const int* in_sizes, int n_in,
                              void* d_out, int out_size) {
    const float* spike = (const float*)d_in[0];   // [64][256][500]
    const float* W1    = (const float*)d_in[1];   // [1024][256]
    const float* W2    = (const float*)d_in[2];   // [18][1024]
    float* out = (float*)d_out;                   // [64][18][500]

    build_lists<<<dim3(N_B, 16), 256>>>(spike);
    transpose_w1<<<dim3(I_DIM / 32, H_DIM / 32), dim3(32, 8)>>>(W1);
    gather_y1<<<dim3(100, 8), 256>>>();
    scan_layer1<<<256, 256>>>();
    gemm2_kernel<<<PAIRS / 64, 256>>>(W2);
    scan_layer2<<<5, 256>>>(out);
}

// round 6
// speedup vs baseline: 2.1756x; 2.1756x over previous
#include <cuda_runtime.h>
#include <cstdint>

// Problem dims
#define N_B   64
#define I_DIM 256
#define H_DIM 1024
#define O_DIM 18
#define T_DIM 500
#define PAIRS (N_B * T_DIM)          // 32000 (n,t) pairs

// Recurrence constants
#define D1 0.9048374180359595f       // exp(-1/10)
#define C1 0.2718281828459045f       // e/10
#define D2 0.36787944117144233f      // exp(-1)
#define C2 2.718281828459045f        // e
#define THETA 10.0f
#define REFSCALE -20.0f              // -scaleRef*theta

// ---- scratch (static device arrays) ----
__device__ float g_W1t[(size_t)I_DIM * H_DIM];                 // W1 transposed [i][h]
__device__ float g_W2t[(size_t)H_DIM * O_DIM];                 // W2 transposed [h][o]
__device__ float g_y1[(size_t)PAIRS * H_DIM];                  // layer-1 pre-psp
__device__ unsigned int g_smask[(size_t)PAIRS * 32];           // s1 spike bitmask [m][h/32]
__device__ float g_y2[(size_t)PAIRS * O_DIM];                  // layer-2 pre-psp
__device__ unsigned char g_lists[(size_t)PAIRS * 256];         // active input idx per (n,t)
__device__ int g_counts[PAIRS];

// ---------------------------------------------------------------------------
// Kernel 1: build per-(n,t) active-input lists from binary spike input.
// ---------------------------------------------------------------------------
__global__ void build_lists(const float* __restrict__ spike) {
    __shared__ float flags[I_DIM][32];
    int n  = blockIdx.x;
    int t0 = blockIdx.y * 32;
    int tid = threadIdx.x;
    int tl  = tid & 31;
    int io  = tid >> 5;

    #pragma unroll 4
    for (int ic = 0; ic < 32; ic++) {
        int i = ic * 8 + io;
        int t = t0 + tl;
        float v = 0.f;
        if (t < T_DIM) v = spike[((size_t)(n * I_DIM + i)) * T_DIM + t];
        flags[i][tl] = v;
    }
    __syncthreads();

    if (tid < 32) {
        int t = t0 + tid;
        if (t < T_DIM) {
            int m = n * T_DIM + t;
            unsigned char* lp = g_lists + (size_t)m * 256;
            int cnt = 0;
            for (int i = 0; i < I_DIM; i++) {
                if (flags[i][tid] != 0.f) lp[cnt++] = (unsigned char)i;
            }
            g_counts[m] = cnt;
        }
    }
}

// ---------------------------------------------------------------------------
// Kernel 2: transpose W1 [H][I] -> W1t [I][H]
// ---------------------------------------------------------------------------
__global__ void transpose_w1(const float* __restrict__ W1) {
    __shared__ float tile[32][33];
    int i0 = blockIdx.x * 32;
    int h0 = blockIdx.y * 32;
    int tx = threadIdx.x, ty = threadIdx.y;   // (32, 8)
    #pragma unroll
    for (int r = 0; r < 32; r += 8)
        tile[ty + r][tx] = W1[(size_t)(h0 + ty + r) * I_DIM + i0 + tx];
    __syncthreads();
    #pragma unroll
    for (int r = 0; r < 32; r += 8)
        g_W1t[(size_t)(i0 + ty + r) * H_DIM + h0 + tx] = tile[tx][ty + r];
}

// ---------------------------------------------------------------------------
// Kernel 2b: transpose W2 [O][H] -> W2t [H][O]
// ---------------------------------------------------------------------------
__global__ void transpose_w2(const float* __restrict__ W2) {
    int idx = blockIdx.x * 256 + threadIdx.x;
    if (idx < O_DIM * H_DIM) {
        int o = idx / H_DIM;
        int h = idx - o * H_DIM;
        g_W2t[(size_t)h * O_DIM + o] = W2[idx];
    }
}

// ---------------------------------------------------------------------------
// Kernel 3: sparse GEMM1, float4 gathers. Warp per m, 32 lanes x float4 = 128 h.
// Grid: (500 m-chunks of 64, 8 h-tiles). W1t slice per block = 128KB (L1-hot).
// ---------------------------------------------------------------------------
__global__ void gather_y1() {
    int warp = threadIdx.x >> 5;
    int lane = threadIdx.x & 31;
    int h4   = blockIdx.y * 32 + lane;        // float4 column index
    const float4* Wt = (const float4*)g_W1t;  // [I][256] float4
    int m0 = blockIdx.x * 64;

    for (int k = 0; k < 8; k++) {
        int m = m0 + warp * 8 + k;
        int cnt = g_counts[m];
        const unsigned char* lp = g_lists + (size_t)m * 256;
        float4 acc = make_float4(0.f, 0.f, 0.f, 0.f);
        int j = 0;
        for (; j + 4 <= cnt; j += 4) {
            uchar4 u = *(const uchar4*)(lp + j);
            float4 a = Wt[(size_t)u.x * (H_DIM / 4) + h4];
            float4 b = Wt[(size_t)u.y * (H_DIM / 4) + h4];
            float4 c = Wt[(size_t)u.z * (H_DIM / 4) + h4];
            float4 d = Wt[(size_t)u.w * (H_DIM / 4) + h4];
            acc.x += a.x; acc.x += b.x; acc.x += c.x; acc.x += d.x;
            acc.y += a.y; acc.y += b.y; acc.y += c.y; acc.y += d.y;
            acc.z += a.z; acc.z += b.z; acc.z += c.z; acc.z += d.z;
            acc.w += a.w; acc.w += b.w; acc.w += c.w; acc.w += d.w;
        }
        for (; j < cnt; j++) {
            float4 a = Wt[(size_t)lp[j] * (H_DIM / 4) + h4];
            acc.x += a.x; acc.y += a.y; acc.z += a.z; acc.w += a.w;
        }
        ((float4*)g_y1)[(size_t)m * (H_DIM / 4) + h4] = acc;
    }
}

// ---------------------------------------------------------------------------
// Kernel 4: fused psp + spike scan, layer 1. Software-pipelined loads (MLP=10).
// Emits s1 as a bitmask via warp ballot (4MB instead of 131MB).
// ---------------------------------------------------------------------------
__global__ void scan_layer1() {
    int n = blockIdx.x >> 2;
    int h = ((blockIdx.x & 3) << 8) + threadIdx.x;
    int lane = threadIdx.x & 31;
    const float* yp = g_y1 + (size_t)n * T_DIM * H_DIM + h;
    unsigned int* mp = g_smask + (size_t)n * T_DIM * 32 + (h >> 5);

    float p1 = 0.f, a1 = 0.f, p2 = 0.f, a2 = 0.f;
    for (int t = 0; t < T_DIM; t += 10) {
        float yy[10];
        #pragma unroll
        for (int k = 0; k < 10; k++)
            yy[k] = yp[(size_t)(t + k) * H_DIM];
        #pragma unroll
        for (int k = 0; k < 10; k++) {
            a1 = D1 * (a1 + p1);
            p1 = D1 * p1 + yy[k];
            a2 = D2 * (a2 + p2);
            float u = C1 * a1 + C2 * a2;
            float s = (u - THETA >= 0.f) ? 1.0f : 0.0f;
            p2 = D2 * p2 + REFSCALE * s;
            unsigned int bal = __ballot_sync(0xffffffffu, s != 0.f);
            if (lane == 0) mp[(size_t)(t + k) * 32] = bal;
        }
    }
}

// ---------------------------------------------------------------------------
// Kernel 5: bit-sparse GEMM2. Warp per m; lanes 0..17 own output o.
// Iterates set bits of the s1 bitmask in ascending h order; W2t is L1-resident.
// ---------------------------------------------------------------------------
__global__ void gemm2_sparse() {
    int warp = threadIdx.x >> 5;
    int lane = threadIdx.x & 31;
    int m = blockIdx.x * 8 + warp;

    unsigned int myword = g_smask[(size_t)m * 32 + lane];
    float acc = 0.f;
    #pragma unroll 4
    for (int src = 0; src < 32; src++) {
        unsigned int word = __shfl_sync(0xffffffffu, myword, src);
        while (word) {
            int b = __ffs(word) - 1;
            word &= word - 1;
            int h = (src << 5) + b;
            if (lane < O_DIM) acc += g_W2t[(size_t)h * O_DIM + lane];
        }
    }
    if (lane < O_DIM) g_y2[(size_t)m * O_DIM + lane] = acc;
}

// ---------------------------------------------------------------------------
// Kernel 6: fused psp + spike scan, layer 2. Pipelined loads. Out [n][o][t].
// ---------------------------------------------------------------------------
__global__ void scan_layer2(float* __restrict__ out) {
    int idx = blockIdx.x * blockDim.x + threadIdx.x;
    if (idx >= N_B * O_DIM) return;
    int n = idx / O_DIM;
    int o = idx - n * O_DIM;
    const float* yp = g_y2 + (size_t)n * T_DIM * O_DIM + o;
    float*       op = out + (size_t)idx * T_DIM;

    float p1 = 0.f, a1 = 0.f, p2 = 0.f, a2 = 0.f;
    for (int t = 0; t < T_DIM; t += 10) {
        float yy[10];
        #pragma unroll
        for (int k = 0; k < 10; k++)
            yy[k] = yp[(size_t)(t + k) * O_DIM];
        #pragma unroll
        for (int k = 0; k < 10; k++) {
            a1 = D1 * (a1 + p1);
            p1 = D1 * p1 + yy[k];
            a2 = D2 * (a2 + p2);
            float u = C1 * a1 + C2 * a2;
            float s = (u - THETA >= 0.f) ? 1.0f : 0.0f;
            p2 = D2 * p2 + REFSCALE * s;
            op[t + k] = s;
        }
    }
}

// ---------------------------------------------------------------------------
extern "C" void kernel_launch(void* const* d_in, const int* in_sizes, int n_in,
                              void* d_out, int out_size) {
    const float* spike = (const float*)d_in[0];   // [64][256][500]
    const float* W1    = (const float*)d_in[1];   // [1024][256]
    const float* W2    = (const float*)d_in[2];   // [18][1024]
    float* out = (float*)d_out;                   // [64][18][500]

    build_lists<<<dim3(N_B, 16), 256>>>(spike);
    transpose_w1<<<dim3(I_DIM / 32, H_DIM / 32), dim3(32, 8)>>>(W1);
    transpose_w2<<<(O_DIM * H_DIM + 255) / 256, 256>>>(W2);
    gather_y1<<<dim3(500, 8), 256>>>();
    scan_layer1<<<256, 256>>>();
    gemm2_sparse<<<PAIRS / 8, 256>>>();
    scan_layer2<<<5, 256>>>(out);
}

// round 9
// speedup vs baseline: 2.3686x; 1.0887x over previous
#include <cuda_runtime.h>
#include <cstdint>

// Problem dims
#define N_B   64
#define I_DIM 256
#define H_DIM 1024
#define O_DIM 18
#define T_DIM 500
#define PAIRS (N_B * T_DIM)          // 32000 (n,t) pairs

// Recurrence constants
#define D1 0.9048374180359595f       // exp(-1/10)
#define C1 0.2718281828459045f       // e/10
#define D2 0.36787944117144233f      // exp(-1)
#define C2 2.718281828459045f        // e
#define THETA 10.0f
#define REFSCALE -20.0f              // -scaleRef*theta

// ---- scratch (static device arrays) ----
__device__ float g_W1t[(size_t)I_DIM * H_DIM];                 // W1 transposed [i][h]
__device__ float g_W2t[(size_t)H_DIM * O_DIM];                 // W2 transposed [h][o]
__device__ float g_y1[(size_t)PAIRS * H_DIM];                  // layer-1 pre-psp
__device__ unsigned int g_smask[(size_t)PAIRS * 32];           // s1 spike bitmask [m][h/32]
__device__ float g_y2[(size_t)PAIRS * O_DIM];                  // layer-2 pre-psp
__device__ unsigned short g_lists[(size_t)PAIRS * 256];        // active idx * 256 per (n,t)
__device__ int g_counts[PAIRS];

// ---------------------------------------------------------------------------
// Kernel 1: build per-(n,t) active-input lists (pre-scaled: value = i * 256 =
// float4-row offset into W1t) from binary spike input.
// ---------------------------------------------------------------------------
__global__ void build_lists(const float* __restrict__ spike) {
    __shared__ float flags[I_DIM][32];
    int n  = blockIdx.x;
    int t0 = blockIdx.y * 32;
    int tid = threadIdx.x;
    int tl  = tid & 31;
    int io  = tid >> 5;

    #pragma unroll 4
    for (int ic = 0; ic < 32; ic++) {
        int i = ic * 8 + io;
        int t = t0 + tl;
        float v = 0.f;
        if (t < T_DIM) v = spike[((size_t)(n * I_DIM + i)) * T_DIM + t];
        flags[i][tl] = v;
    }
    __syncthreads();

    if (tid < 32) {
        int t = t0 + tid;
        if (t < T_DIM) {
            int m = n * T_DIM + t;
            unsigned short* lp = g_lists + (size_t)m * 256;
            int cnt = 0;
            for (int i = 0; i < I_DIM; i++) {
                if (flags[i][tid] != 0.f) lp[cnt++] = (unsigned short)(i << 8);
            }
            // pad to multiple of 4 with repeats of a dummy? NO — keep exact count;
            // tail handled in gather.
            g_counts[m] = cnt;
        }
    }
}

// ---------------------------------------------------------------------------
// Kernel 2: transpose W1 [H][I] -> W1t [I][H]
// ---------------------------------------------------------------------------
__global__ void transpose_w1(const float* __restrict__ W1) {
    __shared__ float tile[32][33];
    int i0 = blockIdx.x * 32;
    int h0 = blockIdx.y * 32;
    int tx = threadIdx.x, ty = threadIdx.y;   // (32, 8)
    #pragma unroll
    for (int r = 0; r < 32; r += 8)
        tile[ty + r][tx] = W1[(size_t)(h0 + ty + r) * I_DIM + i0 + tx];
    __syncthreads();
    #pragma unroll
    for (int r = 0; r < 32; r += 8)
        g_W1t[(size_t)(i0 + ty + r) * H_DIM + h0 + tx] = tile[tx][ty + r];
}

// ---------------------------------------------------------------------------
// Kernel 2b: transpose W2 [O][H] -> W2t [H][O]
// ---------------------------------------------------------------------------
__global__ void transpose_w2(const float* __restrict__ W2) {
    int idx = blockIdx.x * 256 + threadIdx.x;
    if (idx < O_DIM * H_DIM) {
        int o = idx / H_DIM;
        int h = idx - o * H_DIM;
        g_W2t[(size_t)h * O_DIM + o] = W2[idx];
    }
}

// ---------------------------------------------------------------------------
// Kernel 3: sparse GEMM1, float4 gathers with pre-scaled uint16 indices.
// Warp per m, 32 lanes x float4 = 128 h. Addr = Wt + (off + h4): IADD+LDG only.
// ---------------------------------------------------------------------------
__global__ void gather_y1() {
    int warp = threadIdx.x >> 5;
    int lane = threadIdx.x & 31;
    int h4   = blockIdx.y * 32 + lane;        // float4 column index
    const float4* __restrict__ Wt = (const float4*)g_W1t;  // [I][256] float4
    int m0 = blockIdx.x * 64;

    for (int k = 0; k < 8; k++) {
        int m = m0 + warp * 8 + k;
        int cnt = g_counts[m];
        const unsigned short* lp = g_lists + (size_t)m * 256;
        float4 acc = make_float4(0.f, 0.f, 0.f, 0.f);
        int j = 0;
        for (; j + 4 <= cnt; j += 4) {
            ushort4 u = *(const ushort4*)(lp + j);
            float4 a = Wt[(int)u.x + h4];
            float4 b = Wt[(int)u.y + h4];
            float4 c = Wt[(int)u.z + h4];
            float4 d = Wt[(int)u.w + h4];
            acc.x += a.x; acc.x += b.x; acc.x += c.x; acc.x += d.x;
            acc.y += a.y; acc.y += b.y; acc.y += c.y; acc.y += d.y;
            acc.z += a.z; acc.z += b.z; acc.z += c.z; acc.z += d.z;
            acc.w += a.w; acc.w += b.w; acc.w += c.w; acc.w += d.w;
        }
        for (; j < cnt; j++) {
            float4 a = Wt[(int)lp[j] + h4];
            acc.x += a.x; acc.y += a.y; acc.z += a.z; acc.w += a.w;
        }
        ((float4*)g_y1)[(size_t)m * (H_DIM / 4) + h4] = acc;
    }
}

// ---------------------------------------------------------------------------
// Kernel 4: fused psp + spike scan, layer 1. MLP=20. Emits s1 bitmask.
// ---------------------------------------------------------------------------
__global__ void scan_layer1() {
    int n = blockIdx.x >> 2;
    int h = ((blockIdx.x & 3) << 8) + threadIdx.x;
    int lane = threadIdx.x & 31;
    const float* __restrict__ yp = g_y1 + (size_t)n * T_DIM * H_DIM + h;
    unsigned int* mp = g_smask + (size_t)n * T_DIM * 32 + (h >> 5);

    float p1 = 0.f, a1 = 0.f, p2 = 0.f, a2 = 0.f;
    for (int t = 0; t < T_DIM; t += 20) {
        float yy[20];
        #pragma unroll
        for (int k = 0; k < 20; k++)
            yy[k] = yp[(size_t)(t + k) * H_DIM];
        #pragma unroll
        for (int k = 0; k < 20; k++) {
            a1 = D1 * (a1 + p1);
            p1 = D1 * p1 + yy[k];
            a2 = D2 * (a2 + p2);
            float u = C1 * a1 + C2 * a2;
            float s = (u - THETA >= 0.f) ? 1.0f : 0.0f;
            p2 = D2 * p2 + REFSCALE * s;
            unsigned int bal = __ballot_sync(0xffffffffu, s != 0.f);
            if (lane == 0) mp[(size_t)(t + k) * 32] = bal;
        }
    }
}

// ---------------------------------------------------------------------------
// Kernel 5: bit-sparse GEMM2. Warp handles TWO m; merged bit loops overlap
// the two L1-hit load chains. Lanes 0..17 own output o.
// ---------------------------------------------------------------------------
__global__ void gemm2_sparse() {
    int warp = threadIdx.x >> 5;
    int lane = threadIdx.x & 31;
    int m = blockIdx.x * 16 + warp * 2;       // two m per warp

    unsigned int wA = g_smask[(size_t)m * 32 + lane];
    unsigned int wB = g_smask[(size_t)(m + 1) * 32 + lane];
    float accA = 0.f, accB = 0.f;
    bool act = (lane < O_DIM);

    #pragma unroll 4
    for (int src = 0; src < 32; src++) {
        unsigned int a = __shfl_sync(0xffffffffu, wA, src);
        unsigned int b = __shfl_sync(0xffffffffu, wB, src);
        int hb = src << 5;
        while (a | b) {
            if (a) {
                int bit = __ffs(a) - 1; a &= a - 1;
                if (act) accA += g_W2t[(size_t)(hb + bit) * O_DIM + lane];
            }
            if (b) {
                int bit = __ffs(b) - 1; b &= b - 1;
                if (act) accB += g_W2t[(size_t)(hb + bit) * O_DIM + lane];
            }
        }
    }
    if (act) {
        g_y2[(size_t)m * O_DIM + lane] = accA;
        g_y2[(size_t)(m + 1) * O_DIM + lane] = accB;
    }
}

// ---------------------------------------------------------------------------
// Kernel 6: fused psp + spike scan, layer 2. MLP=20. Out [n][o][t].
// ---------------------------------------------------------------------------
__global__ void scan_layer2(float* __restrict__ out) {
    int idx = blockIdx.x * blockDim.x + threadIdx.x;
    if (idx >= N_B * O_DIM) return;
    int n = idx / O_DIM;
    int o = idx - n * O_DIM;
    const float* __restrict__ yp = g_y2 + (size_t)n * T_DIM * O_DIM + o;
    float*       op = out + (size_t)idx * T_DIM;

    float p1 = 0.f, a1 = 0.f, p2 = 0.f, a2 = 0.f;
    for (int t = 0; t < T_DIM; t += 20) {
        float yy[20];
        #pragma unroll
        for (int k = 0; k < 20; k++)
            yy[k] = yp[(size_t)(t + k) * O_DIM];
        #pragma unroll
        for (int k = 0; k < 20; k++) {
            a1 = D1 * (a1 + p1);
            p1 = D1 * p1 + yy[k];
            a2 = D2 * (a2 + p2);
            float u = C1 * a1 + C2 * a2;
            float s = (u - THETA >= 0.f) ? 1.0f : 0.0f;
            p2 = D2 * p2 + REFSCALE * s;
            op[t + k] = s;
        }
    }
}

// ---------------------------------------------------------------------------
extern "C" void kernel_launch(void* const* d_in, const int* in_sizes, int n_in,
                              void* d_out, int out_size) {
    const float* spike = (const float*)d_in[0];   // [64][256][500]
    const float* W1    = (const float*)d_in[1];   // [1024][256]
    const float* W2    = (const float*)d_in[2];   // [18][1024]
    float* out = (float*)d_out;                   // [64][18][500]

    build_lists<<<dim3(N_B, 16), 256>>>(spike);
    transpose_w1<<<dim3(I_DIM / 32, H_DIM / 32), dim3(32, 8)>>>(W1);
    transpose_w2<<<(O_DIM * H_DIM + 255) / 256, 256>>>(W2);
    gather_y1<<<dim3(500, 8), 256>>>();
    scan_layer1<<<256, 256>>>();
    gemm2_sparse<<<PAIRS / 16, 256>>>();
    scan_layer2<<<5, 256>>>(out);
}